// round 8
// baseline (speedup 1.0000x reference)
#include <cuda_runtime.h>
#include <math.h>

#define NB 4
#define NL 4096
#define DIMQ 7168
#define NH 128
#define NK 128
#define DC 512
#define DCQ 1536
#define NR 64

// ---------------- scratch (static device globals; no allocation) ----------------
__device__ float g_qhk[NB * NH * NK];
__device__ float g_qbigp[4 * NB * NH * DCQ];
__device__ float g_qbig[NB * NH * DCQ];
__device__ float g_qr[NB * NH * NR];
__device__ float g_vq[NB * DC * NH];           // [b][d][h]
__device__ float g_kv[(size_t)NB * NL * DC];   // RoPE'd kv cache
__device__ float g_sc[NB * NH * NL];           // scores -> attn (in place)
__device__ float g_part[8 * NB * NH * DC];
__device__ float g_ctxc[NB * NH * DC];
__device__ float g_ctxlat[NB * NH * NK];
__device__ float g_invf[256];

#define FMA2(c, a, b) asm("fma.rn.f32x2 %0, %1, %2, %0;" : "+l"(c) : "l"(a), "l"(b))

__device__ __forceinline__ unsigned long long pack2(float f) {
    unsigned long long u;
    asm("mov.b64 %0, {%1, %1};" : "=l"(u) : "f"(f));
    return u;
}

// ---------------- inv-freq table ----------------
__global__ void k_init_invf() {
    int t = threadIdx.x;
    g_invf[t] = (float)exp(-9.210340371976184 * (double)t / 256.0);
}

// ---------------- RoPE ----------------
__global__ void k_rope(const float* __restrict__ kvc) {
    int bl = blockIdx.x;
    int l = bl & (NL - 1);
    const float* x = kvc + (size_t)bl * DC;
    float* y = g_kv + (size_t)bl * DC;
    int d = threadIdx.x;
    float x1 = x[d], x2 = x[d + 256];
    int j = d >> 1;
    float th1 = (float)l * g_invf[j];
    float th2 = (float)l * g_invf[128 + j];
    float s1, c1, s2, c2;
    sincosf(th1, &s1, &c1);
    sincosf(th2, &s2, &c2);
    y[d]       = x1 * c1 - x2 * s1;
    y[d + 256] = x2 * c2 + x1 * s2;
}

// ---------------- generic 4-row GEMV (R1) ----------------
template <int COLS, int CHUNK>
__global__ __launch_bounds__(256) void k_gemv4(const float* __restrict__ W,
                                               const float* __restrict__ X,
                                               float* __restrict__ Y, int rows) {
    __shared__ float4 xs[NB][CHUNK / 4];
    const int tid = threadIdx.x;
    const int lane = tid & 31, warp = tid >> 5;
    const int row = blockIdx.x * 8 + warp;
    float a0 = 0.f, a1 = 0.f, a2 = 0.f, a3 = 0.f;
    for (int j0 = 0; j0 < COLS; j0 += CHUNK) {
        __syncthreads();
        for (int i = tid; i < NB * (CHUNK / 4); i += 256) {
            int b = i / (CHUNK / 4), j = i % (CHUNK / 4);
            xs[b][j] = reinterpret_cast<const float4*>(X + (size_t)b * COLS + j0)[j];
        }
        __syncthreads();
        const float4* w4 = reinterpret_cast<const float4*>(W + (size_t)row * COLS + j0);
        #pragma unroll 4
        for (int j = lane; j < CHUNK / 4; j += 32) {
            float4 w = w4[j];
            float4 v0 = xs[0][j], v1 = xs[1][j], v2 = xs[2][j], v3 = xs[3][j];
            a0 += w.x * v0.x + w.y * v0.y + w.z * v0.z + w.w * v0.w;
            a1 += w.x * v1.x + w.y * v1.y + w.z * v1.z + w.w * v1.w;
            a2 += w.x * v2.x + w.y * v2.y + w.z * v2.z + w.w * v2.w;
            a3 += w.x * v3.x + w.y * v3.y + w.z * v3.z + w.w * v3.w;
        }
    }
    #pragma unroll
    for (int o = 16; o; o >>= 1) {
        a0 += __shfl_down_sync(0xffffffffu, a0, o);
        a1 += __shfl_down_sync(0xffffffffu, a1, o);
        a2 += __shfl_down_sync(0xffffffffu, a2, o);
        a3 += __shfl_down_sync(0xffffffffu, a3, o);
    }
    if (lane == 0) {
        Y[0 * rows + row] = a0;
        Y[1 * rows + row] = a1;
        Y[2 * rows + row] = a2;
        Y[3 * rows + row] = a3;
    }
}

// ---------------- q_big k-split ----------------
__global__ __launch_bounds__(192) void k_qbig3(const float* __restrict__ w) {
    int h = blockIdx.x, qc = blockIdx.y, kc = blockIdx.z;
    int tid = threadIdx.x;
    __shared__ float qs[NB][32];
    for (int i = tid; i < NB * 32; i += 192)
        qs[i >> 5][i & 31] = g_qhk[(i >> 5) * (NH * NK) + h * NK + kc * 32 + (i & 31)];
    __syncthreads();
    int q = qc * 768 + tid * 4;
    const float4* wp = reinterpret_cast<const float4*>(
        w + ((size_t)h * NK + kc * 32) * DCQ + q);
    float4 a[4];
    #pragma unroll
    for (int b = 0; b < 4; b++) a[b] = make_float4(0.f, 0.f, 0.f, 0.f);
    #pragma unroll 8
    for (int k = 0; k < 32; k++) {
        float4 wv = wp[(size_t)k * (DCQ / 4)];
        #pragma unroll
        for (int b = 0; b < 4; b++) {
            float qv = qs[b][k];
            a[b].x += qv * wv.x; a[b].y += qv * wv.y;
            a[b].z += qv * wv.z; a[b].w += qv * wv.w;
        }
    }
    #pragma unroll
    for (int b = 0; b < 4; b++)
        *reinterpret_cast<float4*>(g_qbigp + (size_t)kc * (NB * NH * DCQ) +
                                   b * (NH * DCQ) + h * DCQ + q) = a[b];
}

__global__ __launch_bounds__(256) void k_qbig_red() {
    int i = blockIdx.x * 1024 + threadIdx.x * 4;
    const int N = NB * NH * DCQ;
    float4 s0 = *reinterpret_cast<float4*>(g_qbigp + i);
    float4 s1 = *reinterpret_cast<float4*>(g_qbigp + N + i);
    float4 s2 = *reinterpret_cast<float4*>(g_qbigp + 2 * N + i);
    float4 s3 = *reinterpret_cast<float4*>(g_qbigp + 3 * N + i);
    *reinterpret_cast<float4*>(g_qbig + i) =
        make_float4(s0.x + s1.x + s2.x + s3.x, s0.y + s1.y + s2.y + s3.y,
                    s0.z + s1.z + s2.z + s3.z, s0.w + s1.w + s2.w + s3.w);
}

// ---------------- q_r ----------------
__global__ __launch_bounds__(256) void k_qr(const float* __restrict__ w) {
    int h = blockIdx.x;
    __shared__ float qs[NB][DCQ];
    __shared__ float part[4][NB][NR];
    for (int i = threadIdx.x; i < NB * DCQ; i += 256) {
        int b = i / DCQ, q = i % DCQ;
        qs[b][q] = g_qbig[b * (NH * DCQ) + h * DCQ + q];
    }
    __syncthreads();
    int qc = threadIdx.x >> 6, r = threadIdx.x & 63;
    float a0 = 0.f, a1 = 0.f, a2 = 0.f, a3 = 0.f;
    const float* wp = w + (size_t)h * DCQ * NR;
    int q0 = qc * 384;
    for (int q = q0; q < q0 + 384; q++) {
        float wv = wp[q * NR + r];
        a0 += qs[0][q] * wv; a1 += qs[1][q] * wv;
        a2 += qs[2][q] * wv; a3 += qs[3][q] * wv;
    }
    part[qc][0][r] = a0; part[qc][1][r] = a1;
    part[qc][2][r] = a2; part[qc][3][r] = a3;
    __syncthreads();
    if (qc == 0) {
        #pragma unroll
        for (int b = 0; b < NB; b++)
            g_qr[b * (NH * NR) + h * NR + r] =
                part[0][b][r] + part[1][b][r] + part[2][b][r] + part[3][b][r];
    }
}

// ---------------- v_q ----------------
__global__ __launch_bounds__(256) void k_vq(const float* __restrict__ w) {
    int h = blockIdx.x;
    __shared__ float qs[NB][NR];
    for (int i = threadIdx.x; i < NB * NR; i += 256)
        qs[i >> 6][i & 63] = g_qr[(i >> 6) * (NH * NR) + h * NR + (i & 63)];
    __syncthreads();
    for (int d = threadIdx.x; d < DC; d += 256) {
        const float4* wp = reinterpret_cast<const float4*>(w + ((size_t)h * DC + d) * NR);
        float a0 = 0.f, a1 = 0.f, a2 = 0.f, a3 = 0.f;
        #pragma unroll
        for (int rv = 0; rv < 16; rv++) {
            float4 wv = wp[rv];
            int r = rv * 4;
            a0 += wv.x * qs[0][r] + wv.y * qs[0][r + 1] + wv.z * qs[0][r + 2] + wv.w * qs[0][r + 3];
            a1 += wv.x * qs[1][r] + wv.y * qs[1][r + 1] + wv.z * qs[1][r + 2] + wv.w * qs[1][r + 3];
            a2 += wv.x * qs[2][r] + wv.y * qs[2][r + 1] + wv.z * qs[2][r + 2] + wv.w * qs[2][r + 3];
            a3 += wv.x * qs[3][r] + wv.y * qs[3][r + 1] + wv.z * qs[3][r + 2] + wv.w * qs[3][r + 3];
        }
        g_vq[0 * (DC * NH) + d * NH + h] = a0;
        g_vq[1 * (DC * NH) + d * NH + h] = a1;
        g_vq[2 * (DC * NH) + d * NH + h] = a2;
        g_vq[3 * (DC * NH) + d * NH + h] = a3;
    }
}

// ---------------- scores: C[h][l] = sum_d vq[d][h] * kv[l][d] ----------------
// block = 128h x 128l, 256 thr (16tx x 16ty), thread tile 8h x 8l (l strided by 16)
__global__ __launch_bounds__(256) void k_scores3() {
    __shared__ float vqs[32 * 128];    // [d][h]
    __shared__ float kvs[128 * 33];    // [l][d] pad 33
    int b = blockIdx.y, l0 = blockIdx.x * 128;
    int tid = threadIdx.x, tx = tid & 15, ty = tid >> 4;
    unsigned long long acc[4][8];
    #pragma unroll
    for (int p = 0; p < 4; p++)
        #pragma unroll
        for (int j = 0; j < 8; j++) acc[p][j] = 0ULL;

    for (int d0 = 0; d0 < DC; d0 += 32) {
        __syncthreads();
        for (int i = tid; i < 32 * 128; i += 256) {
            int d = i >> 7, h = i & 127;
            vqs[i] = g_vq[(b * DC + d0 + d) * NH + h];
        }
        for (int i = tid; i < 128 * 32; i += 256) {
            int l = i >> 5, dd = i & 31;
            kvs[l * 33 + dd] = g_kv[((size_t)(b * NL) + l0 + l) * DC + d0 + dd];
        }
        __syncthreads();
        #pragma unroll 8
        for (int d = 0; d < 32; d++) {
            ulonglong2 a01 = *reinterpret_cast<ulonglong2*>(vqs + d * 128 + ty * 8);
            ulonglong2 a23 = *reinterpret_cast<ulonglong2*>(vqs + d * 128 + ty * 8 + 4);
            unsigned long long bj[8];
            #pragma unroll
            for (int j = 0; j < 8; j++) bj[j] = pack2(kvs[(tx + 16 * j) * 33 + d]);
            #pragma unroll
            for (int j = 0; j < 8; j++) {
                FMA2(acc[0][j], a01.x, bj[j]);
                FMA2(acc[1][j], a01.y, bj[j]);
                FMA2(acc[2][j], a23.x, bj[j]);
                FMA2(acc[3][j], a23.y, bj[j]);
            }
        }
    }
    #pragma unroll
    for (int p = 0; p < 4; p++) {
        int h = ty * 8 + 2 * p;
        #pragma unroll
        for (int j = 0; j < 8; j++) {
            float2 f = *reinterpret_cast<float2*>(&acc[p][j]);
            int l = l0 + tx + 16 * j;
            g_sc[((size_t)(b * NH) + h) * NL + l] = f.x;
            g_sc[((size_t)(b * NH) + h + 1) * NL + l] = f.y;
        }
    }
}

// ---------------- softmax ----------------
__global__ __launch_bounds__(256) void k_softmax() {
    float* p = g_sc + (size_t)blockIdx.x * NL;
    __shared__ float red[8];
    int tid = threadIdx.x, lane = tid & 31, warp = tid >> 5;
    float m = -1e30f;
    for (int i = tid; i < NL; i += 256) m = fmaxf(m, p[i]);
    #pragma unroll
    for (int o = 16; o; o >>= 1) m = fmaxf(m, __shfl_xor_sync(0xffffffffu, m, o));
    if (lane == 0) red[warp] = m;
    __syncthreads();
    float bm = red[0];
    #pragma unroll
    for (int w = 1; w < 8; w++) bm = fmaxf(bm, red[w]);
    __syncthreads();
    float s = 0.f;
    for (int i = tid; i < NL; i += 256) {
        float e = expf(p[i] - bm);
        p[i] = e;
        s += e;
    }
    #pragma unroll
    for (int o = 16; o; o >>= 1) s += __shfl_xor_sync(0xffffffffu, s, o);
    if (lane == 0) red[warp] = s;
    __syncthreads();
    float bs = red[0];
    #pragma unroll
    for (int w = 1; w < 8; w++) bs += red[w];
    float inv = 1.0f / bs;
    for (int i = tid; i < NL; i += 256) p[i] *= inv;
}

// ---------------- ctx: part[ls][h][d] = sum_l attn[h][l] * kv[l][d] ----------------
// block = 128h x 128d, all h in one block (kv read once); 256 thr, tile 8h x 8d
__global__ __launch_bounds__(256) void k_ctx3() {
    __shared__ float atts[32 * 132];   // [l][h] pad 132 (4-way write conflict, ok)
    __shared__ float kvs[32 * 129];    // [l][d] pad 129
    int ls = blockIdx.x, dt = blockIdx.y, b = blockIdx.z;
    int lbase = ls * 512, d0 = dt * 128;
    int tid = threadIdx.x, tx = tid & 15, ty = tid >> 4;
    unsigned long long acc[4][8];
    #pragma unroll
    for (int p = 0; p < 4; p++)
        #pragma unroll
        for (int j = 0; j < 8; j++) acc[p][j] = 0ULL;

    for (int lt = 0; lt < 512; lt += 32) {
        __syncthreads();
        for (int i = tid; i < 32 * 128; i += 256) {
            int l = i >> 7, d = i & 127;
            kvs[l * 129 + d] = g_kv[((size_t)(b * NL) + lbase + lt + l) * DC + d0 + d];
        }
        for (int i = tid; i < 128 * 32; i += 256) {
            int h = i >> 5, l = i & 31;
            atts[l * 132 + h] = g_sc[((size_t)(b * NH) + h) * NL + lbase + lt + l];
        }
        __syncthreads();
        #pragma unroll 8
        for (int l = 0; l < 32; l++) {
            ulonglong2 a01 = *reinterpret_cast<ulonglong2*>(atts + l * 132 + ty * 8);
            ulonglong2 a23 = *reinterpret_cast<ulonglong2*>(atts + l * 132 + ty * 8 + 4);
            unsigned long long bj[8];
            #pragma unroll
            for (int j = 0; j < 8; j++) bj[j] = pack2(kvs[l * 129 + tx + 16 * j]);
            #pragma unroll
            for (int j = 0; j < 8; j++) {
                FMA2(acc[0][j], a01.x, bj[j]);
                FMA2(acc[1][j], a01.y, bj[j]);
                FMA2(acc[2][j], a23.x, bj[j]);
                FMA2(acc[3][j], a23.y, bj[j]);
            }
        }
    }
    #pragma unroll
    for (int p = 0; p < 4; p++) {
        int h = ty * 8 + 2 * p;
        #pragma unroll
        for (int j = 0; j < 8; j++) {
            float2 f = *reinterpret_cast<float2*>(&acc[p][j]);
            int d = d0 + tx + 16 * j;
            g_part[(((size_t)ls * NB + b) * NH + h) * DC + d] = f.x;
            g_part[(((size_t)ls * NB + b) * NH + h + 1) * DC + d] = f.y;
        }
    }
}

__global__ __launch_bounds__(256) void k_ctx_red() {
    int i = blockIdx.x * 256 + threadIdx.x;
    float s = 0.f;
    #pragma unroll
    for (int ls = 0; ls < 8; ls++) s += g_part[(size_t)ls * (NB * NH * DC) + i];
    g_ctxc[i] = s;
}

// ---------------- ctx_lat ----------------
__global__ __launch_bounds__(256) void k_ctxlat(const float* __restrict__ w) {
    int h = blockIdx.x;
    __shared__ float cs[NB][DC];
    int tid = threadIdx.x;
    for (int i = tid; i < NB * DC; i += 256) {
        int bb = i >> 9, d = i & 511;
        cs[bb][d] = g_ctxc[bb * (NH * DC) + h * DC + d];
    }
    __syncthreads();
    int lane = tid & 31, warp = tid >> 5;
    int k = blockIdx.y * 8 + warp;
    const float* wp = w + ((size_t)h * NK + k) * DC;
    float a0 = 0.f, a1 = 0.f, a2 = 0.f, a3 = 0.f;
    for (int d = lane; d < DC; d += 32) {
        float wv = wp[d];
        a0 += cs[0][d] * wv; a1 += cs[1][d] * wv;
        a2 += cs[2][d] * wv; a3 += cs[3][d] * wv;
    }
    #pragma unroll
    for (int o = 16; o; o >>= 1) {
        a0 += __shfl_down_sync(0xffffffffu, a0, o);
        a1 += __shfl_down_sync(0xffffffffu, a1, o);
        a2 += __shfl_down_sync(0xffffffffu, a2, o);
        a3 += __shfl_down_sync(0xffffffffu, a3, o);
    }
    if (lane == 0) {
        g_ctxlat[0 * (NH * NK) + h * NK + k] = a0;
        g_ctxlat[1 * (NH * NK) + h * NK + k] = a1;
        g_ctxlat[2 * (NH * NK) + h * NK + k] = a2;
        g_ctxlat[3 * (NH * NK) + h * NK + k] = a3;
    }
}

extern "C" void kernel_launch(void* const* d_in, const int* in_sizes, int n_in,
                              void* d_out, int out_size) {
    const float* hidden_q = (const float*)d_in[0];
    const float* kv_c     = (const float*)d_in[1];
    const float* Wq       = (const float*)d_in[2];
    const float* w_kc_q   = (const float*)d_in[3];
    const float* w_kc_kv  = (const float*)d_in[4];
    const float* W_qr     = (const float*)d_in[5];
    const float* W_kr     = (const float*)d_in[6];
    const float* Wout     = (const float*)d_in[7];
    float* out = (float*)d_out;

    void* qhk_p = nullptr;
    void* ctxlat_p = nullptr;
    cudaGetSymbolAddress(&qhk_p, g_qhk);
    cudaGetSymbolAddress(&ctxlat_p, g_ctxlat);

    k_init_invf<<<1, 256>>>();
    k_rope<<<NB * NL, 256>>>(kv_c);

    // query chain
    k_gemv4<DIMQ, 1792><<<(NH * NK) / 8, 256>>>(Wq, hidden_q, (float*)qhk_p, NH * NK);
    k_qbig3<<<dim3(NH, 2, 4), 192>>>(w_kc_q);
    k_qbig_red<<<(NB * NH * DCQ) / 1024, 256>>>();
    k_qr<<<NH, 256>>>(W_qr);
    k_vq<<<NH, 256>>>(W_kr);

    // attention
    k_scores3<<<dim3(NL / 128, NB), 256>>>();
    k_softmax<<<NB * NH, 256>>>();
    k_ctx3<<<dim3(8, 4, NB), 256>>>();
    k_ctx_red<<<(NB * NH * DC) / 256, 256>>>();

    // output chain
    k_ctxlat<<<dim3(NH, NK / 8), 256>>>(w_kc_kv);
    k_gemv4<NH * NK, 2048><<<DIMQ / 8, 256>>>(Wout, (const float*)ctxlat_p, out, DIMQ);
}

// round 9
// speedup vs baseline: 1.2488x; 1.2488x over previous
#include <cuda_runtime.h>
#include <math.h>

#define NB 4
#define NL 4096
#define DIMQ 7168
#define NH 128
#define NK 128
#define DC 512
#define DCQ 1536
#define NR 64

// ---------------- scratch (static device globals; no allocation) ----------------
__device__ float g_qhk[NB * NH * NK];
__device__ float g_qbigp[4 * NB * NH * DCQ];
__device__ float g_qbig[NB * NH * DCQ];
__device__ float g_qr[NB * NH * NR];
__device__ float g_vq[NB * DC * NH];           // [b][d][h]
__device__ float g_kv[(size_t)NB * NL * DC];   // RoPE'd kv cache
__device__ float g_sc[NB * NH * NL];           // scores -> attn (in place)
__device__ float g_part[8 * NB * NH * DC];
__device__ float g_ctxc[NB * NH * DC];
__device__ float g_ctxlat[NB * NH * NK];
__device__ float g_invf[256];

#define FMA2(c, a, b) asm("fma.rn.f32x2 %0, %1, %2, %0;" : "+l"(c) : "l"(a), "l"(b))
#define CP_COMMIT() asm volatile("cp.async.commit_group;")
#define CP_WAIT0() asm volatile("cp.async.wait_group 0;")

__device__ __forceinline__ unsigned long long pack2(float f) {
    unsigned long long u;
    asm("mov.b64 %0, {%1, %1};" : "=l"(u) : "f"(f));
    return u;
}

__device__ __forceinline__ void cpa16(unsigned dst, const void* src) {
    asm volatile("cp.async.ca.shared.global [%0], [%1], 16;" :: "r"(dst), "l"(src));
}
__device__ __forceinline__ void cpa8(unsigned dst, const void* src) {
    asm volatile("cp.async.ca.shared.global [%0], [%1], 8;" :: "r"(dst), "l"(src));
}

// ---------------- inv-freq table ----------------
__global__ void k_init_invf() {
    int t = threadIdx.x;
    g_invf[t] = (float)exp(-9.210340371976184 * (double)t / 256.0);
}

// ---------------- RoPE ----------------
__global__ void k_rope(const float* __restrict__ kvc) {
    int bl = blockIdx.x;
    int l = bl & (NL - 1);
    const float* x = kvc + (size_t)bl * DC;
    float* y = g_kv + (size_t)bl * DC;
    int d = threadIdx.x;
    float x1 = x[d], x2 = x[d + 256];
    int j = d >> 1;
    float th1 = (float)l * g_invf[j];
    float th2 = (float)l * g_invf[128 + j];
    float s1, c1, s2, c2;
    sincosf(th1, &s1, &c1);
    sincosf(th2, &s2, &c2);
    y[d]       = x1 * c1 - x2 * s1;
    y[d + 256] = x2 * c2 + x1 * s2;
}

// ---------------- generic 4-row GEMV (R1) ----------------
template <int COLS, int CHUNK>
__global__ __launch_bounds__(256) void k_gemv4(const float* __restrict__ W,
                                               const float* __restrict__ X,
                                               float* __restrict__ Y, int rows) {
    __shared__ float4 xs[NB][CHUNK / 4];
    const int tid = threadIdx.x;
    const int lane = tid & 31, warp = tid >> 5;
    const int row = blockIdx.x * 8 + warp;
    float a0 = 0.f, a1 = 0.f, a2 = 0.f, a3 = 0.f;
    for (int j0 = 0; j0 < COLS; j0 += CHUNK) {
        __syncthreads();
        for (int i = tid; i < NB * (CHUNK / 4); i += 256) {
            int b = i / (CHUNK / 4), j = i % (CHUNK / 4);
            xs[b][j] = reinterpret_cast<const float4*>(X + (size_t)b * COLS + j0)[j];
        }
        __syncthreads();
        const float4* w4 = reinterpret_cast<const float4*>(W + (size_t)row * COLS + j0);
        #pragma unroll 4
        for (int j = lane; j < CHUNK / 4; j += 32) {
            float4 w = w4[j];
            float4 v0 = xs[0][j], v1 = xs[1][j], v2 = xs[2][j], v3 = xs[3][j];
            a0 += w.x * v0.x + w.y * v0.y + w.z * v0.z + w.w * v0.w;
            a1 += w.x * v1.x + w.y * v1.y + w.z * v1.z + w.w * v1.w;
            a2 += w.x * v2.x + w.y * v2.y + w.z * v2.z + w.w * v2.w;
            a3 += w.x * v3.x + w.y * v3.y + w.z * v3.z + w.w * v3.w;
        }
    }
    #pragma unroll
    for (int o = 16; o; o >>= 1) {
        a0 += __shfl_down_sync(0xffffffffu, a0, o);
        a1 += __shfl_down_sync(0xffffffffu, a1, o);
        a2 += __shfl_down_sync(0xffffffffu, a2, o);
        a3 += __shfl_down_sync(0xffffffffu, a3, o);
    }
    if (lane == 0) {
        Y[0 * rows + row] = a0;
        Y[1 * rows + row] = a1;
        Y[2 * rows + row] = a2;
        Y[3 * rows + row] = a3;
    }
}

// ---------------- q_big k-split ----------------
__global__ __launch_bounds__(192) void k_qbig3(const float* __restrict__ w) {
    int h = blockIdx.x, qc = blockIdx.y, kc = blockIdx.z;
    int tid = threadIdx.x;
    __shared__ float qs[NB][32];
    for (int i = tid; i < NB * 32; i += 192)
        qs[i >> 5][i & 31] = g_qhk[(i >> 5) * (NH * NK) + h * NK + kc * 32 + (i & 31)];
    __syncthreads();
    int q = qc * 768 + tid * 4;
    const float4* wp = reinterpret_cast<const float4*>(
        w + ((size_t)h * NK + kc * 32) * DCQ + q);
    float4 a[4];
    #pragma unroll
    for (int b = 0; b < 4; b++) a[b] = make_float4(0.f, 0.f, 0.f, 0.f);
    #pragma unroll 8
    for (int k = 0; k < 32; k++) {
        float4 wv = wp[(size_t)k * (DCQ / 4)];
        #pragma unroll
        for (int b = 0; b < 4; b++) {
            float qv = qs[b][k];
            a[b].x += qv * wv.x; a[b].y += qv * wv.y;
            a[b].z += qv * wv.z; a[b].w += qv * wv.w;
        }
    }
    #pragma unroll
    for (int b = 0; b < 4; b++)
        *reinterpret_cast<float4*>(g_qbigp + (size_t)kc * (NB * NH * DCQ) +
                                   b * (NH * DCQ) + h * DCQ + q) = a[b];
}

__global__ __launch_bounds__(256) void k_qbig_red() {
    int i = blockIdx.x * 1024 + threadIdx.x * 4;
    const int N = NB * NH * DCQ;
    float4 s0 = *reinterpret_cast<float4*>(g_qbigp + i);
    float4 s1 = *reinterpret_cast<float4*>(g_qbigp + N + i);
    float4 s2 = *reinterpret_cast<float4*>(g_qbigp + 2 * N + i);
    float4 s3 = *reinterpret_cast<float4*>(g_qbigp + 3 * N + i);
    *reinterpret_cast<float4*>(g_qbig + i) =
        make_float4(s0.x + s1.x + s2.x + s3.x, s0.y + s1.y + s2.y + s3.y,
                    s0.z + s1.z + s2.z + s3.z, s0.w + s1.w + s2.w + s3.w);
}

// ---------------- q_r ----------------
__global__ __launch_bounds__(256) void k_qr(const float* __restrict__ w) {
    int h = blockIdx.x;
    __shared__ float qs[NB][DCQ];
    __shared__ float part[4][NB][NR];
    for (int i = threadIdx.x; i < NB * DCQ; i += 256) {
        int b = i / DCQ, q = i % DCQ;
        qs[b][q] = g_qbig[b * (NH * DCQ) + h * DCQ + q];
    }
    __syncthreads();
    int qc = threadIdx.x >> 6, r = threadIdx.x & 63;
    float a0 = 0.f, a1 = 0.f, a2 = 0.f, a3 = 0.f;
    const float* wp = w + (size_t)h * DCQ * NR;
    int q0 = qc * 384;
    for (int q = q0; q < q0 + 384; q++) {
        float wv = wp[q * NR + r];
        a0 += qs[0][q] * wv; a1 += qs[1][q] * wv;
        a2 += qs[2][q] * wv; a3 += qs[3][q] * wv;
    }
    part[qc][0][r] = a0; part[qc][1][r] = a1;
    part[qc][2][r] = a2; part[qc][3][r] = a3;
    __syncthreads();
    if (qc == 0) {
        #pragma unroll
        for (int b = 0; b < NB; b++)
            g_qr[b * (NH * NR) + h * NR + r] =
                part[0][b][r] + part[1][b][r] + part[2][b][r] + part[3][b][r];
    }
}

// ---------------- v_q ----------------
__global__ __launch_bounds__(256) void k_vq(const float* __restrict__ w) {
    int h = blockIdx.x;
    __shared__ float qs[NB][NR];
    for (int i = threadIdx.x; i < NB * NR; i += 256)
        qs[i >> 6][i & 63] = g_qr[(i >> 6) * (NH * NR) + h * NR + (i & 63)];
    __syncthreads();
    for (int d = threadIdx.x; d < DC; d += 256) {
        const float4* wp = reinterpret_cast<const float4*>(w + ((size_t)h * DC + d) * NR);
        float a0 = 0.f, a1 = 0.f, a2 = 0.f, a3 = 0.f;
        #pragma unroll
        for (int rv = 0; rv < 16; rv++) {
            float4 wv = wp[rv];
            int r = rv * 4;
            a0 += wv.x * qs[0][r] + wv.y * qs[0][r + 1] + wv.z * qs[0][r + 2] + wv.w * qs[0][r + 3];
            a1 += wv.x * qs[1][r] + wv.y * qs[1][r + 1] + wv.z * qs[1][r + 2] + wv.w * qs[1][r + 3];
            a2 += wv.x * qs[2][r] + wv.y * qs[2][r + 1] + wv.z * qs[2][r + 2] + wv.w * qs[2][r + 3];
            a3 += wv.x * qs[3][r] + wv.y * qs[3][r + 1] + wv.z * qs[3][r + 2] + wv.w * qs[3][r + 3];
        }
        g_vq[0 * (DC * NH) + d * NH + h] = a0;
        g_vq[1 * (DC * NH) + d * NH + h] = a1;
        g_vq[2 * (DC * NH) + d * NH + h] = a2;
        g_vq[3 * (DC * NH) + d * NH + h] = a3;
    }
}

// ---------------- scores: C[h][l] = sum_d vq[d][h] * kv[l][d] ----------------
// pipelined 128h x 128l, cp.async double buffer, thread tile 8h x 8l
#define SC_BUF (4096 + 128 * 34)
__global__ __launch_bounds__(256) void k_scores_p() {
    extern __shared__ float sm[];
    int b = blockIdx.y, l0 = blockIdx.x * 128;
    int tid = threadIdx.x, tx = tid & 15, ty = tid >> 4;
    unsigned sbase = (unsigned)__cvta_generic_to_shared(sm);
    unsigned long long acc[4][8];
    #pragma unroll
    for (int p = 0; p < 4; p++)
        #pragma unroll
        for (int j = 0; j < 8; j++) acc[p][j] = 0ULL;

    // issue copy of k-chunk k0 into buffer p
    auto issue_copy = [&](int p, int k0) {
        unsigned vdst = sbase + (unsigned)(p * SC_BUF) * 4u;
        const float* vsrc = g_vq + (b * DC + k0 * 32) * NH;
        #pragma unroll
        for (int c = 0; c < 4; c++) {
            int idx = c * 256 + tid;
            int d = idx >> 5, h4 = idx & 31;
            cpa16(vdst + (unsigned)(d * 128 + h4 * 4) * 4u, vsrc + d * NH + h4 * 4);
        }
        unsigned kdst = sbase + (unsigned)(p * SC_BUF + 4096) * 4u;
        const float* ksrc = g_kv + ((size_t)(b * NL) + l0) * DC + k0 * 32;
        #pragma unroll
        for (int c = 0; c < 8; c++) {
            int idx = c * 256 + tid;
            int l = idx >> 4, c8 = idx & 15;
            cpa8(kdst + (unsigned)(l * 34 + c8 * 2) * 4u, ksrc + (size_t)l * DC + c8 * 2);
        }
    };

    issue_copy(0, 0);
    CP_COMMIT();
    CP_WAIT0();
    __syncthreads();

    for (int k0 = 0; k0 < 16; k0++) {
        int cur = k0 & 1;
        if (k0 + 1 < 16) {
            issue_copy(1 - cur, k0 + 1);
            CP_COMMIT();
        }
        float* vqs = sm + cur * SC_BUF;
        float* kvs = sm + cur * SC_BUF + 4096;
        #pragma unroll 4
        for (int d = 0; d < 32; d++) {
            ulonglong2 a01 = *reinterpret_cast<ulonglong2*>(vqs + d * 128 + ty * 8);
            ulonglong2 a23 = *reinterpret_cast<ulonglong2*>(vqs + d * 128 + ty * 8 + 4);
            unsigned long long bj[8];
            #pragma unroll
            for (int j = 0; j < 8; j++) bj[j] = pack2(kvs[(tx + 16 * j) * 34 + d]);
            #pragma unroll
            for (int j = 0; j < 8; j++) {
                FMA2(acc[0][j], a01.x, bj[j]);
                FMA2(acc[1][j], a01.y, bj[j]);
                FMA2(acc[2][j], a23.x, bj[j]);
                FMA2(acc[3][j], a23.y, bj[j]);
            }
        }
        CP_WAIT0();
        __syncthreads();
    }

    #pragma unroll
    for (int p = 0; p < 4; p++) {
        int h = ty * 8 + 2 * p;
        #pragma unroll
        for (int j = 0; j < 8; j++) {
            float2 f = *reinterpret_cast<float2*>(&acc[p][j]);
            int l = l0 + tx + 16 * j;
            g_sc[((size_t)(b * NH) + h) * NL + l] = f.x;
            g_sc[((size_t)(b * NH) + h + 1) * NL + l] = f.y;
        }
    }
}

// ---------------- softmax ----------------
__global__ __launch_bounds__(256) void k_softmax() {
    float* p = g_sc + (size_t)blockIdx.x * NL;
    __shared__ float red[8];
    int tid = threadIdx.x, lane = tid & 31, warp = tid >> 5;
    float m = -1e30f;
    for (int i = tid; i < NL; i += 256) m = fmaxf(m, p[i]);
    #pragma unroll
    for (int o = 16; o; o >>= 1) m = fmaxf(m, __shfl_xor_sync(0xffffffffu, m, o));
    if (lane == 0) red[warp] = m;
    __syncthreads();
    float bm = red[0];
    #pragma unroll
    for (int w = 1; w < 8; w++) bm = fmaxf(bm, red[w]);
    __syncthreads();
    float s = 0.f;
    for (int i = tid; i < NL; i += 256) {
        float e = expf(p[i] - bm);
        p[i] = e;
        s += e;
    }
    #pragma unroll
    for (int o = 16; o; o >>= 1) s += __shfl_xor_sync(0xffffffffu, s, o);
    if (lane == 0) red[warp] = s;
    __syncthreads();
    float bs = red[0];
    #pragma unroll
    for (int w = 1; w < 8; w++) bs += red[w];
    float inv = 1.0f / bs;
    for (int i = tid; i < NL; i += 256) p[i] *= inv;
}

// ---------------- ctx: part[ls][h][d] = sum_l attn[h][l] * kv[l][d] ----------------
// pipelined 128h x 128d, cp.async kv + register-prefetch attn, thread tile 8h x 8d
#define CX_BUF (4096 + 32 * 132)
__global__ __launch_bounds__(256) void k_ctx_p() {
    extern __shared__ float sm[];
    int ls = blockIdx.x, dt = blockIdx.y, b = blockIdx.z;
    int lbase = ls * 512, d0 = dt * 128;
    int tid = threadIdx.x, tx = tid & 15, ty = tid >> 4;
    unsigned sbase = (unsigned)__cvta_generic_to_shared(sm);
    unsigned long long acc[4][8];
    #pragma unroll
    for (int p = 0; p < 4; p++)
        #pragma unroll
        for (int j = 0; j < 8; j++) acc[p][j] = 0ULL;

    auto issue_kvs = [&](int p, int lt) {
        unsigned kdst = sbase + (unsigned)(p * CX_BUF) * 4u;
        const float* ksrc = g_kv + ((size_t)(b * NL) + lbase + lt) * DC + d0;
        #pragma unroll
        for (int c = 0; c < 4; c++) {
            int idx = c * 256 + tid;
            int l = idx >> 5, d4 = idx & 31;
            cpa16(kdst + (unsigned)(l * 128 + d4 * 4) * 4u, ksrc + (size_t)l * DC + d4 * 4);
        }
    };
    auto ldg_atts = [&](int lt, float4* r) {
        #pragma unroll
        for (int c = 0; c < 4; c++) {
            int idx = c * 256 + tid;
            int h = idx >> 3, c4 = idx & 7;
            r[c] = *reinterpret_cast<const float4*>(
                g_sc + ((size_t)(b * NH) + h) * NL + lbase + lt + c4 * 4);
        }
    };
    auto store_atts = [&](int p, float4* r) {
        float* atts = sm + p * CX_BUF + 4096;
        #pragma unroll
        for (int c = 0; c < 4; c++) {
            int idx = c * 256 + tid;
            int h = idx >> 3, c4 = idx & 7;
            atts[(c4 * 4 + 0) * 132 + h] = r[c].x;
            atts[(c4 * 4 + 1) * 132 + h] = r[c].y;
            atts[(c4 * 4 + 2) * 132 + h] = r[c].z;
            atts[(c4 * 4 + 3) * 132 + h] = r[c].w;
        }
    };

    float4 ra[4];
    issue_kvs(0, 0);
    CP_COMMIT();
    ldg_atts(0, ra);
    store_atts(0, ra);
    CP_WAIT0();
    __syncthreads();

    for (int it = 0; it < 16; it++) {
        int cur = it & 1;
        if (it + 1 < 16) {
            issue_kvs(1 - cur, (it + 1) * 32);
            CP_COMMIT();
            ldg_atts((it + 1) * 32, ra);
        }
        float* kvs = sm + cur * CX_BUF;
        float* atts = sm + cur * CX_BUF + 4096;
        #pragma unroll 4
        for (int l = 0; l < 32; l++) {
            ulonglong2 a01 = *reinterpret_cast<ulonglong2*>(atts + l * 132 + ty * 8);
            ulonglong2 a23 = *reinterpret_cast<ulonglong2*>(atts + l * 132 + ty * 8 + 4);
            unsigned long long bj[8];
            #pragma unroll
            for (int j = 0; j < 8; j++) bj[j] = pack2(kvs[l * 128 + tx + 16 * j]);
            #pragma unroll
            for (int j = 0; j < 8; j++) {
                FMA2(acc[0][j], a01.x, bj[j]);
                FMA2(acc[1][j], a01.y, bj[j]);
                FMA2(acc[2][j], a23.x, bj[j]);
                FMA2(acc[3][j], a23.y, bj[j]);
            }
        }
        if (it + 1 < 16) store_atts(1 - cur, ra);
        CP_WAIT0();
        __syncthreads();
    }

    #pragma unroll
    for (int p = 0; p < 4; p++) {
        int h = ty * 8 + 2 * p;
        #pragma unroll
        for (int j = 0; j < 8; j++) {
            float2 f = *reinterpret_cast<float2*>(&acc[p][j]);
            int d = d0 + tx + 16 * j;
            g_part[(((size_t)ls * NB + b) * NH + h) * DC + d] = f.x;
            g_part[(((size_t)ls * NB + b) * NH + h + 1) * DC + d] = f.y;
        }
    }
}

__global__ __launch_bounds__(256) void k_ctx_red() {
    int i = blockIdx.x * 256 + threadIdx.x;
    float s = 0.f;
    #pragma unroll
    for (int ls = 0; ls < 8; ls++) s += g_part[(size_t)ls * (NB * NH * DC) + i];
    g_ctxc[i] = s;
}

// ---------------- ctx_lat ----------------
__global__ __launch_bounds__(256) void k_ctxlat(const float* __restrict__ w) {
    int h = blockIdx.x;
    __shared__ float cs[NB][DC];
    int tid = threadIdx.x;
    for (int i = tid; i < NB * DC; i += 256) {
        int bb = i >> 9, d = i & 511;
        cs[bb][d] = g_ctxc[bb * (NH * DC) + h * DC + d];
    }
    __syncthreads();
    int lane = tid & 31, warp = tid >> 5;
    int k = blockIdx.y * 8 + warp;
    const float* wp = w + ((size_t)h * NK + k) * DC;
    float a0 = 0.f, a1 = 0.f, a2 = 0.f, a3 = 0.f;
    for (int d = lane; d < DC; d += 32) {
        float wv = wp[d];
        a0 += cs[0][d] * wv; a1 += cs[1][d] * wv;
        a2 += cs[2][d] * wv; a3 += cs[3][d] * wv;
    }
    #pragma unroll
    for (int o = 16; o; o >>= 1) {
        a0 += __shfl_down_sync(0xffffffffu, a0, o);
        a1 += __shfl_down_sync(0xffffffffu, a1, o);
        a2 += __shfl_down_sync(0xffffffffu, a2, o);
        a3 += __shfl_down_sync(0xffffffffu, a3, o);
    }
    if (lane == 0) {
        g_ctxlat[0 * (NH * NK) + h * NK + k] = a0;
        g_ctxlat[1 * (NH * NK) + h * NK + k] = a1;
        g_ctxlat[2 * (NH * NK) + h * NK + k] = a2;
        g_ctxlat[3 * (NH * NK) + h * NK + k] = a3;
    }
}

extern "C" void kernel_launch(void* const* d_in, const int* in_sizes, int n_in,
                              void* d_out, int out_size) {
    const float* hidden_q = (const float*)d_in[0];
    const float* kv_c     = (const float*)d_in[1];
    const float* Wq       = (const float*)d_in[2];
    const float* w_kc_q   = (const float*)d_in[3];
    const float* w_kc_kv  = (const float*)d_in[4];
    const float* W_qr     = (const float*)d_in[5];
    const float* W_kr     = (const float*)d_in[6];
    const float* Wout     = (const float*)d_in[7];
    float* out = (float*)d_out;

    void* qhk_p = nullptr;
    void* ctxlat_p = nullptr;
    cudaGetSymbolAddress(&qhk_p, g_qhk);
    cudaGetSymbolAddress(&ctxlat_p, g_ctxlat);

    cudaFuncSetAttribute(k_scores_p, cudaFuncAttributeMaxDynamicSharedMemorySize,
                         2 * SC_BUF * 4);
    cudaFuncSetAttribute(k_ctx_p, cudaFuncAttributeMaxDynamicSharedMemorySize,
                         2 * CX_BUF * 4);

    k_init_invf<<<1, 256>>>();
    k_rope<<<NB * NL, 256>>>(kv_c);

    // query chain
    k_gemv4<DIMQ, 1792><<<(NH * NK) / 8, 256>>>(Wq, hidden_q, (float*)qhk_p, NH * NK);
    k_qbig3<<<dim3(NH, 2, 4), 192>>>(w_kc_q);
    k_qbig_red<<<(NB * NH * DCQ) / 1024, 256>>>();
    k_qr<<<NH, 256>>>(W_qr);
    k_vq<<<NH, 256>>>(W_kr);

    // attention
    k_scores_p<<<dim3(NL / 128, NB), 256, 2 * SC_BUF * 4>>>();
    k_softmax<<<NB * NH, 256>>>();
    k_ctx_p<<<dim3(8, 4, NB), 256, 2 * CX_BUF * 4>>>();
    k_ctx_red<<<(NB * NH * DC) / 256, 256>>>();

    // output chain
    k_ctxlat<<<dim3(NH, NK / 8), 256>>>(w_kc_kv);
    k_gemv4<NH * NK, 2048><<<DIMQ / 8, 256>>>(Wout, (const float*)ctxlat_p, out, DIMQ);
}